// round 2
// baseline (speedup 1.0000x reference)
#include <cuda_runtime.h>
#include <math.h>

#define BB 32
#define DIN 1024
#define DOUT 1024
#define BETA 0.9f
#define LEAK 0.9f

#define KTILE 128
#define NSPLIT (DIN / KTILE)   /* 8 */
#define JTILE 128
#define NJT (DOUT / JTILE)     /* 8 */

/* output offsets (floats), in reference return order:
   s, E_W2, E_b2, Rh_W2, Rh_b2, g_bar2, r2 */
#define OFF_S  0
#define OFF_EW (BB * DOUT)                       /* 32768 */
#define OFF_EB (OFF_EW + BB * DIN * DOUT)        /* 33587200 */
#define OFF_RW (OFF_EB + BB * DOUT)              /* 33619968 */
#define OFF_RB (OFF_RW + BB * DIN * DOUT)        /* 67174400 */
#define OFF_G  (OFF_RB + BB * DOUT)              /* 67207168 */
#define OFF_R  (OFF_G + BB * DOUT)               /* 67239936 */

__device__ float g_hpart[NSPLIT][BB * DOUT];     /* 1 MB scratch, fully rewritten every call */

/* ---------------- kernel 1: split-K GEMM, h partials ------------------- */
/* grid (NJT, NSPLIT), 128 threads. Each thread owns one j column and keeps
   all 32 batch accumulators in registers; x tile lives in smem (broadcast
   LDS, conflict-free). W tile is read exactly once -> 4 MB total W traffic. */
__global__ void __launch_bounds__(128) gemm_partial(const float* __restrict__ x,
                                                    const float* __restrict__ W) {
    __shared__ float xs[BB][KTILE];              /* 16 KB */
    const int jt  = blockIdx.x;
    const int ks  = blockIdx.y;
    const int tid = threadIdx.x;
    const int j   = jt * JTILE + tid;
    const int k0  = ks * KTILE;

    for (int idx = tid; idx < BB * KTILE; idx += 128) {
        int bb = idx / KTILE, kk = idx % KTILE;
        xs[bb][kk] = x[bb * DIN + k0 + kk];
    }
    __syncthreads();

    float acc[BB];
#pragma unroll
    for (int bb = 0; bb < BB; bb++) acc[bb] = 0.0f;

    for (int kk = 0; kk < KTILE; kk += 4) {
        const float w0 = W[(k0 + kk + 0) * DOUT + j];
        const float w1 = W[(k0 + kk + 1) * DOUT + j];
        const float w2 = W[(k0 + kk + 2) * DOUT + j];
        const float w3 = W[(k0 + kk + 3) * DOUT + j];
#pragma unroll
        for (int bb = 0; bb < BB; bb++) {
            float4 xv = *(const float4*)&xs[bb][kk];
            acc[bb] = fmaf(xv.x, w0, acc[bb]);
            acc[bb] = fmaf(xv.y, w1, acc[bb]);
            acc[bb] = fmaf(xv.z, w2, acc[bb]);
            acc[bb] = fmaf(xv.w, w3, acc[bb]);
        }
    }

#pragma unroll
    for (int bb = 0; bb < BB; bb++)
        g_hpart[ks][bb * DOUT + j] = acc[bb];
}

/* ---------------- kernel 2: activation + all small outputs ------------- */
__global__ void __launch_bounds__(256) act_small(const float* __restrict__ bias,
                                                 const float* __restrict__ u,
                                                 const float* __restrict__ E_b,
                                                 const float* __restrict__ Rh_b,
                                                 const float* __restrict__ g_bar,
                                                 const float* __restrict__ r,
                                                 float* __restrict__ out) {
    const int idx = blockIdx.x * 256 + threadIdx.x;   /* 0..32767 */
    const int bb = idx >> 10;
    const int j  = idx & 1023;

    float h = bias[j];
#pragma unroll
    for (int ks = 0; ks < NSPLIT; ks++) h += g_hpart[ks][idx];

    const float un = BETA * u[idx] + h;
    const float s  = 1.0f / (1.0f + expf(-(un - 1.0f)));
    const float sg = s * (1.0f - s);
    const float a  = BETA * sg;                        /* ds_du */

    out[OFF_S + idx] = s;

    const float eb1 = BETA * E_b[idx] + 1.0f;
    out[OFF_EB + idx] = BETA * eb1 + 1.0f;             /* E_b2 */
    const float dthb = a * eb1 + sg;
    out[OFF_RB + idx] = a * Rh_b[idx] + dthb;          /* Rh_b2 */

    const float ratio0 = LEAK * r[bb];
    const float r2 = ratio0 + 1.0f;
    const float ratio = ratio0 / r2;
    out[OFF_G + idx] = ratio * g_bar[idx] + (1.0f - ratio) * a;  /* g_bar2 */
    if (j == 0) out[OFF_R + bb] = r2;
}

/* ---------------- kernel 3: big streaming trace update ----------------- */
/* One float4 per thread: 32 B in (E_W, Rh_W), 32 B out (E_W2, Rh_W2).
   s is re-read from d_out (L2 hit); x[b,i] is warp-uniform. */
__global__ void __launch_bounds__(256) big_update(const float* __restrict__ x,
                                                  const float4* __restrict__ E_W,
                                                  const float4* __restrict__ Rh_W,
                                                  float* __restrict__ out) {
    const float4* __restrict__ s4p = (const float4*)(out + OFF_S);
    float4* __restrict__ ew2 = (float4*)(out + OFF_EW);
    float4* __restrict__ rw2 = (float4*)(out + OFF_RW);

    const int idx = blockIdx.x * 256 + threadIdx.x;   /* 0..8388607 */
    const int bb  = idx >> 18;                         /* /(1024*256) */
    const int rem = idx & 262143;
    const int i   = rem >> 8;
    const int j4  = rem & 255;

    const float  xv = __ldg(&x[bb * DIN + i]);
    const float4 s4 = s4p[bb * 256 + j4];
    const float4 ew = E_W[idx];
    const float4 rh = Rh_W[idx];

    float4 o1, o2;

    {
        const float sg = s4.x * (1.0f - s4.x);
        const float a  = BETA * sg;
        const float e1 = fmaf(BETA, ew.x, xv);
        o1.x = fmaf(BETA, e1, xv);
        o2.x = fmaf(a, rh.x, fmaf(a, e1, xv * sg));
    }
    {
        const float sg = s4.y * (1.0f - s4.y);
        const float a  = BETA * sg;
        const float e1 = fmaf(BETA, ew.y, xv);
        o1.y = fmaf(BETA, e1, xv);
        o2.y = fmaf(a, rh.y, fmaf(a, e1, xv * sg));
    }
    {
        const float sg = s4.z * (1.0f - s4.z);
        const float a  = BETA * sg;
        const float e1 = fmaf(BETA, ew.z, xv);
        o1.z = fmaf(BETA, e1, xv);
        o2.z = fmaf(a, rh.z, fmaf(a, e1, xv * sg));
    }
    {
        const float sg = s4.w * (1.0f - s4.w);
        const float a  = BETA * sg;
        const float e1 = fmaf(BETA, ew.w, xv);
        o1.w = fmaf(BETA, e1, xv);
        o2.w = fmaf(a, rh.w, fmaf(a, e1, xv * sg));
    }

    ew2[idx] = o1;
    rw2[idx] = o2;
}

extern "C" void kernel_launch(void* const* d_in, const int* in_sizes, int n_in,
                              void* d_out, int out_size) {
    const float* x     = (const float*)d_in[0];
    const float* W     = (const float*)d_in[1];
    const float* bias  = (const float*)d_in[2];
    const float* u     = (const float*)d_in[3];
    const float* E_W   = (const float*)d_in[4];
    const float* E_b   = (const float*)d_in[5];
    const float* Rh_W  = (const float*)d_in[6];
    const float* Rh_b  = (const float*)d_in[7];
    const float* g_bar = (const float*)d_in[8];
    const float* r     = (const float*)d_in[9];
    float* out = (float*)d_out;

    dim3 gg(NJT, NSPLIT);
    gemm_partial<<<gg, 128>>>(x, W);
    act_small<<<BB * DOUT / 256, 256>>>(bias, u, E_b, Rh_b, g_bar, r, out);
    big_update<<<(BB * DIN * DOUT / 4) / 256, 256>>>(x, (const float4*)E_W,
                                                     (const float4*)Rh_W, out);
}

// round 3
// speedup vs baseline: 1.2172x; 1.2172x over previous
#include <cuda_runtime.h>
#include <math.h>

#define BB 32
#define DIN 1024
#define DOUT 1024
#define BETA 0.9f
#define LEAK 0.9f

#define KTILE 32
#define NSPLIT (DIN / KTILE)   /* 32 */
#define JTILE 128
#define NJT (DOUT / JTILE)     /* 8 */

/* output offsets (floats), in reference return order:
   s, E_W2, E_b2, Rh_W2, Rh_b2, g_bar2, r2 */
#define OFF_S  0
#define OFF_EW (BB * DOUT)
#define OFF_EB (OFF_EW + BB * DIN * DOUT)
#define OFF_RW (OFF_EB + BB * DOUT)
#define OFF_RB (OFF_RW + BB * DIN * DOUT)
#define OFF_G  (OFF_RB + BB * DOUT)
#define OFF_R  (OFF_G + BB * DOUT)

__device__ float g_hpart[NSPLIT][BB * DOUT];     /* 4 MB scratch, fully rewritten every call */

/* ---------------- kernel 1: split-K GEMM, h partials ------------------- */
/* grid (NJT=8, NSPLIT=32) = 256 blocks, 128 threads. Each thread owns one j
   column and keeps all 32 batch accumulators in registers; x tile in smem.
   W tile is read exactly once -> 4 MB total W traffic. */
__global__ void __launch_bounds__(128) gemm_partial(const float* __restrict__ x,
                                                    const float* __restrict__ W) {
    __shared__ float xs[BB][KTILE];              /* 4 KB */
    const int jt  = blockIdx.x;
    const int ks  = blockIdx.y;
    const int tid = threadIdx.x;
    const int j   = jt * JTILE + tid;
    const int k0  = ks * KTILE;

#pragma unroll
    for (int idx = tid; idx < BB * KTILE; idx += 128) {
        int bb = idx / KTILE, kk = idx % KTILE;
        xs[bb][kk] = x[bb * DIN + k0 + kk];
    }
    __syncthreads();

    float acc[BB];
#pragma unroll
    for (int bb = 0; bb < BB; bb++) acc[bb] = 0.0f;

#pragma unroll
    for (int kk = 0; kk < KTILE; kk += 4) {
        const float w0 = W[(k0 + kk + 0) * DOUT + j];
        const float w1 = W[(k0 + kk + 1) * DOUT + j];
        const float w2 = W[(k0 + kk + 2) * DOUT + j];
        const float w3 = W[(k0 + kk + 3) * DOUT + j];
#pragma unroll
        for (int bb = 0; bb < BB; bb++) {
            float4 xv = *(const float4*)&xs[bb][kk];
            acc[bb] = fmaf(xv.x, w0, acc[bb]);
            acc[bb] = fmaf(xv.y, w1, acc[bb]);
            acc[bb] = fmaf(xv.z, w2, acc[bb]);
            acc[bb] = fmaf(xv.w, w3, acc[bb]);
        }
    }

#pragma unroll
    for (int bb = 0; bb < BB; bb++)
        g_hpart[ks][bb * DOUT + j] = acc[bb];
}

/* ---------------- kernel 2: activation + all small outputs ------------- */
__global__ void __launch_bounds__(256) act_small(const float* __restrict__ bias,
                                                 const float* __restrict__ u,
                                                 const float* __restrict__ E_b,
                                                 const float* __restrict__ Rh_b,
                                                 const float* __restrict__ g_bar,
                                                 const float* __restrict__ r,
                                                 float* __restrict__ out) {
    const int idx = blockIdx.x * 256 + threadIdx.x;   /* 0..32767 */
    const int bb = idx >> 10;
    const int j  = idx & 1023;

    float h = bias[j];
#pragma unroll
    for (int ks = 0; ks < NSPLIT; ks++) h += g_hpart[ks][idx];

    const float un = BETA * u[idx] + h;
    const float s  = 1.0f / (1.0f + expf(-(un - 1.0f)));
    const float sg = s * (1.0f - s);
    const float a  = BETA * sg;                        /* ds_du */

    out[OFF_S + idx] = s;

    const float eb1 = BETA * E_b[idx] + 1.0f;
    out[OFF_EB + idx] = BETA * eb1 + 1.0f;             /* E_b2 */
    const float dthb = a * eb1 + sg;
    out[OFF_RB + idx] = a * Rh_b[idx] + dthb;          /* Rh_b2 */

    const float ratio0 = LEAK * r[bb];
    const float r2 = ratio0 + 1.0f;
    const float ratio = ratio0 / r2;
    out[OFF_G + idx] = ratio * g_bar[idx] + (1.0f - ratio) * a;  /* g_bar2 */
    if (j == 0) out[OFF_R + bb] = r2;
}

/* ---------------- kernel 3: big streaming trace update ----------------- */
/* One float4 per thread: 32 B in (E_W, Rh_W), 32 B out (E_W2, Rh_W2).
   s is re-read from d_out (L2 hit); x[b,i] is warp-uniform. */
__global__ void __launch_bounds__(256) big_update(const float* __restrict__ x,
                                                  const float4* __restrict__ E_W,
                                                  const float4* __restrict__ Rh_W,
                                                  float* __restrict__ out) {
    const float4* __restrict__ s4p = (const float4*)(out + OFF_S);
    float4* __restrict__ ew2 = (float4*)(out + OFF_EW);
    float4* __restrict__ rw2 = (float4*)(out + OFF_RW);

    const int idx = blockIdx.x * 256 + threadIdx.x;   /* 0..8388607 */
    const int bb  = idx >> 18;
    const int rem = idx & 262143;
    const int i   = rem >> 8;
    const int j4  = rem & 255;

    /* DRAM streams first for max MLP */
    const float4 ew = E_W[idx];
    const float4 rh = Rh_W[idx];
    const float  xv = __ldg(&x[bb * DIN + i]);
    const float4 s4 = s4p[bb * 256 + j4];

    float4 o1, o2;

    {
        const float sg = s4.x * (1.0f - s4.x);
        const float a  = BETA * sg;
        const float e1 = fmaf(BETA, ew.x, xv);
        o1.x = fmaf(BETA, e1, xv);
        o2.x = fmaf(a, rh.x, fmaf(a, e1, xv * sg));
    }
    {
        const float sg = s4.y * (1.0f - s4.y);
        const float a  = BETA * sg;
        const float e1 = fmaf(BETA, ew.y, xv);
        o1.y = fmaf(BETA, e1, xv);
        o2.y = fmaf(a, rh.y, xv * sg) + a * e1;
    }
    {
        const float sg = s4.z * (1.0f - s4.z);
        const float a  = BETA * sg;
        const float e1 = fmaf(BETA, ew.z, xv);
        o1.z = fmaf(BETA, e1, xv);
        o2.z = fmaf(a, rh.z, fmaf(a, e1, xv * sg));
    }
    {
        const float sg = s4.w * (1.0f - s4.w);
        const float a  = BETA * sg;
        const float e1 = fmaf(BETA, ew.w, xv);
        o1.w = fmaf(BETA, e1, xv);
        o2.w = fmaf(a, rh.w, fmaf(a, e1, xv * sg));
    }
    /* keep y-lane math identical to others (fix ordering to match) */
    {
        const float sg = s4.y * (1.0f - s4.y);
        const float a  = BETA * sg;
        const float e1 = fmaf(BETA, ew.y, xv);
        o2.y = fmaf(a, rh.y, fmaf(a, e1, xv * sg));
    }

    ew2[idx] = o1;
    rw2[idx] = o2;
}

extern "C" void kernel_launch(void* const* d_in, const int* in_sizes, int n_in,
                              void* d_out, int out_size) {
    const float* x     = (const float*)d_in[0];
    const float* W     = (const float*)d_in[1];
    const float* bias  = (const float*)d_in[2];
    const float* u     = (const float*)d_in[3];
    const float* E_W   = (const float*)d_in[4];
    const float* E_b   = (const float*)d_in[5];
    const float* Rh_W  = (const float*)d_in[6];
    const float* Rh_b  = (const float*)d_in[7];
    const float* g_bar = (const float*)d_in[8];
    const float* r     = (const float*)d_in[9];
    float* out = (float*)d_out;

    dim3 gg(NJT, NSPLIT);
    gemm_partial<<<gg, 128>>>(x, W);
    act_small<<<BB * DOUT / 256, 256>>>(bias, u, E_b, Rh_b, g_bar, r, out);
    big_update<<<(BB * DIN * DOUT / 4) / 256, 256>>>(x, (const float4*)E_W,
                                                     (const float4*)Rh_W, out);
}

// round 4
// speedup vs baseline: 1.2689x; 1.0425x over previous
#include <cuda_runtime.h>
#include <math.h>

#define BB 32
#define DIN 1024
#define DOUT 1024
#define BETA 0.9f
#define LEAK 0.9f

#define KTILE 16
#define NSPLIT (DIN / KTILE)   /* 64 */
#define JTILE 128
#define NJT (DOUT / JTILE)     /* 8 */
#define BSPLIT 2
#define BHALF (BB / BSPLIT)    /* 16 */

/* output offsets (floats), in reference return order:
   s, E_W2, E_b2, Rh_W2, Rh_b2, g_bar2, r2 */
#define OFF_S  0
#define OFF_EW (BB * DOUT)
#define OFF_EB (OFF_EW + BB * DIN * DOUT)
#define OFF_RW (OFF_EB + BB * DOUT)
#define OFF_RB (OFF_RW + BB * DIN * DOUT)
#define OFF_G  (OFF_RB + BB * DOUT)
#define OFF_R  (OFF_G + BB * DOUT)

__device__ float g_hpart[NSPLIT][BB * DOUT];     /* 8 MB scratch, fully rewritten every call */

/* ---------------- kernel 1: split-K GEMM, h partials ------------------- */
/* grid (NJT=8, NSPLIT=64, BSPLIT=2) = 1024 blocks, 128 threads. Each thread
   owns one j column and 16 batch accumulators; x tile in smem. */
__global__ void __launch_bounds__(128) gemm_partial(const float* __restrict__ x,
                                                    const float* __restrict__ W) {
    __shared__ float xs[BHALF][KTILE];           /* 1 KB */
    const int jt  = blockIdx.x;
    const int ks  = blockIdx.y;
    const int bs  = blockIdx.z;
    const int tid = threadIdx.x;
    const int j   = jt * JTILE + tid;
    const int k0  = ks * KTILE;
    const int b0  = bs * BHALF;

    if (tid < BHALF * KTILE) {                   /* 256 elems, 2 per thread */
        int bb = tid / KTILE, kk = tid % KTILE;
        xs[bb][kk] = x[(b0 + bb) * DIN + k0 + kk];
    }
    {
        int t2 = tid + 128;
        if (t2 < BHALF * KTILE) {
            int bb = t2 / KTILE, kk = t2 % KTILE;
            xs[bb][kk] = x[(b0 + bb) * DIN + k0 + kk];
        }
    }
    __syncthreads();

    float acc[BHALF];
#pragma unroll
    for (int bb = 0; bb < BHALF; bb++) acc[bb] = 0.0f;

#pragma unroll
    for (int kk = 0; kk < KTILE; kk += 4) {
        const float w0 = W[(k0 + kk + 0) * DOUT + j];
        const float w1 = W[(k0 + kk + 1) * DOUT + j];
        const float w2 = W[(k0 + kk + 2) * DOUT + j];
        const float w3 = W[(k0 + kk + 3) * DOUT + j];
#pragma unroll
        for (int bb = 0; bb < BHALF; bb++) {
            float4 xv = *(const float4*)&xs[bb][kk];
            acc[bb] = fmaf(xv.x, w0, acc[bb]);
            acc[bb] = fmaf(xv.y, w1, acc[bb]);
            acc[bb] = fmaf(xv.z, w2, acc[bb]);
            acc[bb] = fmaf(xv.w, w3, acc[bb]);
        }
    }

#pragma unroll
    for (int bb = 0; bb < BHALF; bb++)
        g_hpart[ks][(b0 + bb) * DOUT + j] = acc[bb];
}

/* ---------------- kernel 2: activation + all small outputs ------------- */
__global__ void __launch_bounds__(256) act_small(const float* __restrict__ bias,
                                                 const float* __restrict__ u,
                                                 const float* __restrict__ E_b,
                                                 const float* __restrict__ Rh_b,
                                                 const float* __restrict__ g_bar,
                                                 const float* __restrict__ r,
                                                 float* __restrict__ out) {
    const int idx = blockIdx.x * 256 + threadIdx.x;   /* 0..32767 */
    const int bb = idx >> 10;
    const int j  = idx & 1023;

    float h = bias[j];
#pragma unroll
    for (int ks = 0; ks < NSPLIT; ks++) h += g_hpart[ks][idx];

    const float un = BETA * u[idx] + h;
    const float s  = 1.0f / (1.0f + expf(-(un - 1.0f)));
    const float sg = s * (1.0f - s);
    const float a  = BETA * sg;                        /* ds_du */

    out[OFF_S + idx] = s;

    const float eb1 = BETA * E_b[idx] + 1.0f;
    out[OFF_EB + idx] = BETA * eb1 + 1.0f;             /* E_b2 */
    const float dthb = a * eb1 + sg;
    out[OFF_RB + idx] = a * Rh_b[idx] + dthb;          /* Rh_b2 */

    const float ratio0 = LEAK * r[bb];
    const float r2 = ratio0 + 1.0f;
    const float ratio = ratio0 / r2;
    out[OFF_G + idx] = ratio * g_bar[idx] + (1.0f - ratio) * a;  /* g_bar2 */
    if (j == 0) out[OFF_R + bb] = r2;
}

/* ---------------- kernel 3: big streaming trace update ----------------- */
/* One float4 per thread: 32 B in (E_W, Rh_W), 32 B out (E_W2, Rh_W2).
   Streaming cache hints keep the 512 MB streams from churning L2 so the
   s / x reads stay L2-resident. */
__global__ void __launch_bounds__(256) big_update(const float* __restrict__ x,
                                                  const float4* __restrict__ E_W,
                                                  const float4* __restrict__ Rh_W,
                                                  float* __restrict__ out) {
    const float4* __restrict__ s4p = (const float4*)(out + OFF_S);
    float4* __restrict__ ew2 = (float4*)(out + OFF_EW);
    float4* __restrict__ rw2 = (float4*)(out + OFF_RW);

    const int idx = blockIdx.x * 256 + threadIdx.x;   /* 0..8388607 */
    const int bb  = idx >> 18;
    const int rem = idx & 262143;
    const int i   = rem >> 8;
    const int j4  = rem & 255;

    /* DRAM streams first for max MLP, evict-first policy */
    const float4 ew = __ldcs(&E_W[idx]);
    const float4 rh = __ldcs(&Rh_W[idx]);
    const float  xv = __ldg(&x[bb * DIN + i]);
    const float4 s4 = s4p[bb * 256 + j4];

    float4 o1, o2;

    {
        const float sg = s4.x * (1.0f - s4.x);
        const float a  = BETA * sg;
        const float e1 = fmaf(BETA, ew.x, xv);
        o1.x = fmaf(BETA, e1, xv);
        o2.x = fmaf(a, rh.x, fmaf(a, e1, xv * sg));
    }
    {
        const float sg = s4.y * (1.0f - s4.y);
        const float a  = BETA * sg;
        const float e1 = fmaf(BETA, ew.y, xv);
        o1.y = fmaf(BETA, e1, xv);
        o2.y = fmaf(a, rh.y, fmaf(a, e1, xv * sg));
    }
    {
        const float sg = s4.z * (1.0f - s4.z);
        const float a  = BETA * sg;
        const float e1 = fmaf(BETA, ew.z, xv);
        o1.z = fmaf(BETA, e1, xv);
        o2.z = fmaf(a, rh.z, fmaf(a, e1, xv * sg));
    }
    {
        const float sg = s4.w * (1.0f - s4.w);
        const float a  = BETA * sg;
        const float e1 = fmaf(BETA, ew.w, xv);
        o1.w = fmaf(BETA, e1, xv);
        o2.w = fmaf(a, rh.w, fmaf(a, e1, xv * sg));
    }

    __stcs(&ew2[idx], o1);
    __stcs(&rw2[idx], o2);
}

extern "C" void kernel_launch(void* const* d_in, const int* in_sizes, int n_in,
                              void* d_out, int out_size) {
    const float* x     = (const float*)d_in[0];
    const float* W     = (const float*)d_in[1];
    const float* bias  = (const float*)d_in[2];
    const float* u     = (const float*)d_in[3];
    const float* E_W   = (const float*)d_in[4];
    const float* E_b   = (const float*)d_in[5];
    const float* Rh_W  = (const float*)d_in[6];
    const float* Rh_b  = (const float*)d_in[7];
    const float* g_bar = (const float*)d_in[8];
    const float* r     = (const float*)d_in[9];
    float* out = (float*)d_out;

    dim3 gg(NJT, NSPLIT, BSPLIT);
    gemm_partial<<<gg, 128>>>(x, W);
    act_small<<<BB * DOUT / 256, 256>>>(bias, u, E_b, Rh_b, g_bar, r, out);
    big_update<<<(BB * DIN * DOUT / 4) / 256, 256>>>(x, (const float4*)E_W,
                                                     (const float4*)Rh_W, out);
}